// round 4
// baseline (speedup 1.0000x reference)
#include <cuda_runtime.h>
#include <math.h>

#define B 32
#define N 1024
#define D 2048   // IMG_DIM
#define E 1024   // EMBED
#define CHUNKS 16
#define CROWS (N / CHUNKS)   // 64 rows per chunk, 8 per warp

// ---------------- scratch (device globals) ----------------
__device__ float g_v[B * D];                // v[b,d] = sum_e ws1_w[e,d]*cap[b,e]
__device__ float g_scores[B * N];           // raw logits (valid prefix only)
__device__ float g_part[B * CHUNKS * D];    // per-chunk weighted partial sums
__device__ float g_pm[B * CHUNKS];          // per-chunk running max
__device__ float g_pl[B * CHUNKS];          // per-chunk exp-sum
__device__ float g_x[B * D];                // attention-pooled features
__device__ float g_outfeat[B * E];          // x @ ws1_w^T + ws1_b
__device__ float g_feats[B * E];            // outfeat @ fc_w^T + fc_b

// ---------------- K0: zero g_v, init bias accumulators ----------------
__global__ void k0_init(const float* __restrict__ ws1_b, const float* __restrict__ fc_b) {
    int i = blockIdx.x * 256 + threadIdx.x;
    if (i < B * D) g_v[i] = 0.0f;
    else if (i < B * D + B * E) { int j = i - B * D;         g_outfeat[j] = ws1_b[j & (E - 1)]; }
    else                        { int j = i - B * D - B * E; g_feats[j]   = fc_b[j & (E - 1)]; }
}

// ---------------- K1: v[b,d] += sum_e cap[b,e]*W1[e,d] ----------------
#define K1_EC 64
__global__ __launch_bounds__(128) void k1_v(const float* __restrict__ cap,
                                            const float* __restrict__ W1) {
    __shared__ float sc[8][K1_EC];
    int tid = threadIdx.x;
    int d  = blockIdx.x * 512 + tid * 4;
    int e0 = blockIdx.y * K1_EC;
    int b0 = blockIdx.z * 8;
    for (int i = tid; i < 8 * K1_EC; i += 128)
        sc[i >> 6][i & 63] = cap[(b0 + (i >> 6)) * E + e0 + (i & 63)];
    __syncthreads();
    float4 acc[8];
#pragma unroll
    for (int r = 0; r < 8; r++) acc[r] = make_float4(0.f, 0.f, 0.f, 0.f);
#pragma unroll 4
    for (int e = 0; e < K1_EC; e++) {
        float4 wv = *(const float4*)(W1 + (size_t)(e0 + e) * D + d);
#pragma unroll
        for (int r = 0; r < 8; r++) {
            float c = sc[r][e];
            acc[r].x += c * wv.x; acc[r].y += c * wv.y;
            acc[r].z += c * wv.z; acc[r].w += c * wv.w;
        }
    }
#pragma unroll
    for (int r = 0; r < 8; r++) {
        float* p = &g_v[(size_t)(b0 + r) * D + d];
        atomicAdd(p + 0, acc[r].x); atomicAdd(p + 1, acc[r].y);
        atomicAdd(p + 2, acc[r].z); atomicAdd(p + 3, acc[r].w);
    }
}

// ---------------- K2: fused scores + online-softmax pooling (single pass) ----
// Block = (chunk, b), 256 threads = 8 warps. Warp w owns rows n0+w+8t.
// Full row lives in 64 registers: dot, warp-reduce, and accumulate all local
// to the warp -> no intra-row barriers, 16 LDG.128 in flight per row.
__global__ __launch_bounds__(256) void k2_fused(const float* __restrict__ img,
                                                const int* __restrict__ len) {
    __shared__ float sv[D];             // 8KB
    __shared__ float sbuf[4][D];        // 32KB combine staging
    __shared__ float pm[8], pl[8];

    int chunk = blockIdx.x, b = blockIdx.y;
    int L  = __ldg(&len[b]);
    int n0 = chunk * CROWS;
    int tid = threadIdx.x, warp = tid >> 5, lane = tid & 31;

    if (n0 >= L) {                       // fully-invalid chunk: record empty, exit
        if (tid == 0) { g_pm[b * CHUNKS + chunk] = -INFINITY; g_pl[b * CHUNKS + chunk] = 0.f; }
        return;
    }

    for (int i = tid; i < D; i += 256) sv[i] = g_v[b * D + i];
    __syncthreads();

    const float4* sv4 = (const float4*)sv;
    float4 acc[16];
#pragma unroll
    for (int j = 0; j < 16; j++) acc[j] = make_float4(0.f, 0.f, 0.f, 0.f);
    float m = -INFINITY, l = 0.f;

    for (int t = 0; t < CROWS / 8; t++) {           // 8 rows per warp max
        int n = n0 + warp + 8 * t;
        if (n >= L) break;                          // warp-uniform
        const float4* row = (const float4*)(img + ((size_t)b * N + n) * D);
        float4 r[16];
        float dot = 0.f;
#pragma unroll
        for (int j = 0; j < 16; j++) {
            r[j] = row[j * 32 + lane];
            float4 v = sv4[j * 32 + lane];
            dot += r[j].x * v.x + r[j].y * v.y + r[j].z * v.z + r[j].w * v.w;
        }
#pragma unroll
        for (int o = 16; o; o >>= 1) dot += __shfl_xor_sync(0xffffffffu, dot, o);
        if (lane == 0) g_scores[b * N + n] = dot;
        if (dot > m) {
            float sc = __expf(m - dot);             // m=-inf -> 0 (first row OK)
            l *= sc;
#pragma unroll
            for (int j = 0; j < 16; j++) {
                acc[j].x *= sc; acc[j].y *= sc; acc[j].z *= sc; acc[j].w *= sc;
            }
            m = dot;
        }
        float e = __expf(dot - m);
        l += e;
#pragma unroll
        for (int j = 0; j < 16; j++) {
            acc[j].x += e * r[j].x; acc[j].y += e * r[j].y;
            acc[j].z += e * r[j].z; acc[j].w += e * r[j].w;
        }
    }

    if (lane == 0) { pm[warp] = m; pl[warp] = l; }
    __syncthreads();

    // block max / sum, scale own accumulator
    float mblk = -INFINITY;
#pragma unroll
    for (int w = 0; w < 8; w++) mblk = fmaxf(mblk, pm[w]);
    float lblk = 0.f;
#pragma unroll
    for (int w = 0; w < 8; w++)
        lblk += ((pl[w] > 0.f) ? __expf(pm[w] - mblk) : 0.f) * pl[w];
    float myfac = (l > 0.f) ? __expf(m - mblk) : 0.f;
#pragma unroll
    for (int j = 0; j < 16; j++) {
        acc[j].x *= myfac; acc[j].y *= myfac; acc[j].z *= myfac; acc[j].w *= myfac;
    }

    // tree-merge 8 warps through 4 smem buffers
    float4* buf = (float4*)sbuf[warp & 3];
    if (warp < 4) {
#pragma unroll
        for (int j = 0; j < 16; j++) buf[j * 32 + lane] = acc[j];
    }
    __syncthreads();
    if (warp >= 4) {
#pragma unroll
        for (int j = 0; j < 16; j++) {
            float4 v = buf[j * 32 + lane];
            v.x += acc[j].x; v.y += acc[j].y; v.z += acc[j].z; v.w += acc[j].w;
            buf[j * 32 + lane] = v;
        }
    }
    __syncthreads();

    float* part = g_part + (size_t)(b * CHUNKS + chunk) * D;
    for (int i = tid; i < D / 4; i += 256) {        // 2 iterations
        float4 a0 = ((const float4*)sbuf[0])[i];
        float4 a1 = ((const float4*)sbuf[1])[i];
        float4 a2 = ((const float4*)sbuf[2])[i];
        float4 a3 = ((const float4*)sbuf[3])[i];
        float4 o;
        o.x = a0.x + a1.x + a2.x + a3.x;
        o.y = a0.y + a1.y + a2.y + a3.y;
        o.z = a0.z + a1.z + a2.z + a3.z;
        o.w = a0.w + a1.w + a2.w + a3.w;
        ((float4*)part)[i] = o;
    }
    if (tid == 0) { g_pm[b * CHUNKS + chunk] = mblk; g_pl[b * CHUNKS + chunk] = lblk; }
}

// ---------------- K3: merge chunk partials -> g_x; emit attention weights ---
// grid (B, 4): each block owns 512 d-elements; dsplit 0 also emits attn.
__global__ __launch_bounds__(128) void k3_merge(const int* __restrict__ len,
                                                float* __restrict__ attn_out) {
    __shared__ float sm_[CHUNKS], sl_[CHUNKS];
    int b = blockIdx.x, ds = blockIdx.y, tid = threadIdx.x;
    if (tid < CHUNKS) { sm_[tid] = g_pm[b * CHUNKS + tid]; sl_[tid] = g_pl[b * CHUNKS + tid]; }
    __syncthreads();
    float M = -INFINITY;
#pragma unroll
    for (int c = 0; c < CHUNKS; c++) M = fmaxf(M, sm_[c]);
    float fac[CHUNKS]; float Lsum = 0.f;
#pragma unroll
    for (int c = 0; c < CHUNKS; c++) {
        fac[c] = (sl_[c] > 0.f) ? __expf(sm_[c] - M) : 0.f;
        Lsum += fac[c] * sl_[c];
    }
    float invL = 1.0f / Lsum;

    int i = ds * 128 + tid;                        // float4 index into D/4=512
    float4 a = make_float4(0.f, 0.f, 0.f, 0.f);
#pragma unroll
    for (int c = 0; c < CHUNKS; c++) {
        float f = fac[c];
        if (f != 0.f) {
            float4 p = ((const float4*)g_part)[(size_t)(b * CHUNKS + c) * (D / 4) + i];
            a.x += f * p.x; a.y += f * p.y; a.z += f * p.z; a.w += f * p.w;
        }
    }
    a.x *= invL; a.y *= invL; a.z *= invL; a.w *= invL;
    ((float4*)g_x)[b * (D / 4) + i] = a;

    if (ds == 0) {
        int Lb = __ldg(&len[b]);
        for (int n = tid; n < N; n += 128)
            attn_out[b * N + n] = (n < Lb) ? __expf(g_scores[b * N + n] - M) * invL : 0.f;
    }
}

// ---------------- GEMV body: out[b,e] += sum_k A[b,k]*W[e,k] -----------------
#define KL 256
__device__ __forceinline__ void gemv32_body(const float* __restrict__ A,
                                            const float* __restrict__ W,
                                            float* __restrict__ out, int K) {
    __shared__ float sA[B * KL];
    int k0 = blockIdx.y * KL;
    for (int i = threadIdx.x; i < B * KL; i += 256) {
        int row = i >> 8, col = i & (KL - 1);
        sA[i] = A[row * K + k0 + col];
    }
    __syncthreads();
    int warp = threadIdx.x >> 5, lane = threadIdx.x & 31;
    int e = blockIdx.x * 8 + warp;
    const float4* w4 = (const float4*)(W + (size_t)e * K + k0);
    float acc[B];
#pragma unroll
    for (int b = 0; b < B; b++) acc[b] = 0.f;
#pragma unroll
    for (int j = 0; j < KL / 128; j++) {
        float4 wv = w4[lane + 32 * j];
#pragma unroll
        for (int b = 0; b < B; b++) {
            float4 a = *(const float4*)(sA + b * KL + (lane + 32 * j) * 4);
            acc[b] += wv.x * a.x + wv.y * a.y + wv.z * a.z + wv.w * a.w;
        }
    }
    float mine = 0.f;
#pragma unroll
    for (int b = 0; b < B; b++) {
        float v = acc[b];
#pragma unroll
        for (int o = 16; o; o >>= 1) v += __shfl_xor_sync(0xffffffffu, v, o);
        if (lane == b) mine = v;
    }
    atomicAdd(&out[lane * E + e], mine);
}

__global__ __launch_bounds__(256) void k5_gemv(const float* __restrict__ W) {
    gemv32_body(g_x, W, g_outfeat, D);
}
__global__ __launch_bounds__(256) void k6_gemv(const float* __restrict__ W) {
    gemv32_body(g_outfeat, W, g_feats, E);
}

// ---------------- K7: l2 normalize, write features output --------------------
__global__ __launch_bounds__(256) void k7_norm(float* __restrict__ out) {
    int b = blockIdx.x;
    __shared__ float red[8];
    int wid = threadIdx.x >> 5, lane = threadIdx.x & 31;
    float s = 0.f;
    for (int i = threadIdx.x; i < E; i += 256) {
        float v = g_feats[b * E + i];
        s += v * v;
    }
#pragma unroll
    for (int o = 16; o; o >>= 1) s += __shfl_xor_sync(0xffffffffu, s, o);
    if (lane == 0) red[wid] = s;
    __syncthreads();
    if (threadIdx.x == 0) {
        float t = 0.f;
#pragma unroll
        for (int i = 0; i < 8; i++) t += red[i];
        red[0] = 1.0f / sqrtf(t);
    }
    __syncthreads();
    float inv = red[0];
    for (int i = threadIdx.x; i < E; i += 256)
        out[b * E + i] = g_feats[b * E + i] * inv;
}

// ---------------- launch ------------------------------------------------------
extern "C" void kernel_launch(void* const* d_in, const int* in_sizes, int n_in,
                              void* d_out, int out_size) {
    const float* images = (const float*)d_in[0];  // [B,N,D]
    const float* cap    = (const float*)d_in[1];  // [B,E]
    const int*   len    = (const int*)  d_in[2];  // [B]
    const float* ws1_w  = (const float*)d_in[3];  // [E,D]
    const float* ws1_b  = (const float*)d_in[4];  // [E]
    const float* fc_w   = (const float*)d_in[5];  // [E,E]
    const float* fc_b   = (const float*)d_in[6];  // [E]
    float* out_features = (float*)d_out;          // [B,E]
    float* out_attn     = (float*)d_out + B * E;  // [B,N,1]

    k0_init<<<(B * D + 2 * B * E + 255) / 256, 256>>>(ws1_b, fc_b);
    k1_v<<<dim3(4, 16, 4), 128>>>(cap, ws1_w);
    k2_fused<<<dim3(CHUNKS, B), 256>>>(images, len);
    k3_merge<<<dim3(B, 4), 128>>>(len, out_attn);
    k5_gemv<<<dim3(E / 8, D / KL), 256>>>(ws1_w);
    k6_gemv<<<dim3(E / 8, E / KL), 256>>>(fc_w);
    k7_norm<<<B, 256>>>(out_features);
}